// round 14
// baseline (speedup 1.0000x reference)
#include <cuda_runtime.h>
#include <cuda_bf16.h>
#include <cstdint>
#include <math.h>

#define T_LEN 512
#define B_SZ  128
#define NG    768
#define WHS 260
#define HSS 260
#define BG_CTAS 32
#define HROW(r) ((r) * HSS + (((r) >> 2) << 2))

// fused-kernel smem layout (floats)
#define SM_WH   0                      // [24][260]  recurrent weights
#define SM_WX   6240                   // [24][260]  input-proj weights (role B)
#define SM_TILE 12480                  // skewed [32 rows] tile (h or x), 8352 floats
#define SM_RED  20832                  // [4 ks][64 pos][16]
#define SM_TOT  24928                  // 99712 bytes

// ---------------- scratch ----------------
__device__ float    g_xA [(size_t)T_LEN * B_SZ * 256];
__device__ float    g_xB [(size_t)T_LEN * B_SZ * 256];
__device__ float    g_xp [(size_t)T_LEN * B_SZ * NG];
__device__ unsigned g_bar[4 * T_LEN * 4];          // [layer][t][bg]

// ---------------- embedding ----------------
__global__ void embed_kernel(const int* __restrict__ tokens, const float* __restrict__ emb,
                             float* __restrict__ xout) {
    int gid = blockIdx.x * blockDim.x + threadIdx.x;
    int row = gid >> 6;
    int c4  = gid & 63;
    int t = row >> 7;
    int b = row & 127;
    int tok = tokens[b * T_LEN + t];
    const float4* e4 = reinterpret_cast<const float4*>(emb);
    float4*       x4 = reinterpret_cast<float4*>(xout);
    x4[(size_t)row * 64 + c4] = e4[(size_t)tok * 64 + c4];
}

// ---------------- input projection GEMM (proven: 520us, fma 62%) ----------------
__global__ __launch_bounds__(256) void proj_kernel(const float* __restrict__ W,
                                                   const float* __restrict__ bias,
                                                   const float* __restrict__ xin,
                                                   float* __restrict__ xpout) {
    __shared__ float As[16][128];
    __shared__ float Bs[16][128];
    int m0 = blockIdx.x * 128;
    int n0 = blockIdx.y * 128;
    int tid = threadIdx.x;
    int tx = tid & 15, ty = tid >> 4;
    float acc[8][8] = {};

    for (int k0 = 0; k0 < 256; k0 += 16) {
        #pragma unroll
        for (int i = 0; i < 2; i++) {
            int fid = tid + i * 256;
            int m   = fid >> 2;
            int kv  = fid & 3;
            float4 v = *reinterpret_cast<const float4*>(
                &xin[(size_t)(m0 + m) * 256 + k0 + kv * 4]);
            As[kv * 4 + 0][m] = v.x; As[kv * 4 + 1][m] = v.y;
            As[kv * 4 + 2][m] = v.z; As[kv * 4 + 3][m] = v.w;
        }
        #pragma unroll
        for (int i = 0; i < 2; i++) {
            int fid = tid + i * 256;
            int kr  = fid >> 5;
            int nc  = fid & 31;
            *reinterpret_cast<float4*>(&Bs[kr][nc * 4]) =
                *reinterpret_cast<const float4*>(&W[(size_t)(k0 + kr) * NG + n0 + nc * 4]);
        }
        __syncthreads();
        #pragma unroll
        for (int kk = 0; kk < 16; kk++) {
            float4 b0 = *reinterpret_cast<const float4*>(&Bs[kk][tx * 4]);
            float4 b1 = *reinterpret_cast<const float4*>(&Bs[kk][64 + tx * 4]);
            float a[8];
            #pragma unroll
            for (int i = 0; i < 8; i++) a[i] = As[kk][ty * 8 + i];
            #pragma unroll
            for (int i = 0; i < 8; i++) {
                acc[i][0] = fmaf(a[i], b0.x, acc[i][0]);
                acc[i][1] = fmaf(a[i], b0.y, acc[i][1]);
                acc[i][2] = fmaf(a[i], b0.z, acc[i][2]);
                acc[i][3] = fmaf(a[i], b0.w, acc[i][3]);
                acc[i][4] = fmaf(a[i], b1.x, acc[i][4]);
                acc[i][5] = fmaf(a[i], b1.y, acc[i][5]);
                acc[i][6] = fmaf(a[i], b1.z, acc[i][6]);
                acc[i][7] = fmaf(a[i], b1.w, acc[i][7]);
            }
        }
        __syncthreads();
    }
    {
        int nA = n0 + tx * 4;
        int nB = n0 + 64 + tx * 4;
        float4 biasA = *reinterpret_cast<const float4*>(&bias[nA]);
        float4 biasB = *reinterpret_cast<const float4*>(&bias[nB]);
        #pragma unroll
        for (int i = 0; i < 8; i++) {
            size_t m = (size_t)(m0 + ty * 8 + i);
            float4 oA = make_float4(acc[i][0] + biasA.x, acc[i][1] + biasA.y,
                                    acc[i][2] + biasA.z, acc[i][3] + biasA.w);
            float4 oB = make_float4(acc[i][4] + biasB.x, acc[i][5] + biasB.y,
                                    acc[i][6] + biasB.z, acc[i][7] + biasB.w);
            *reinterpret_cast<float4*>(&xpout[m * NG + nA]) = oA;
            *reinterpret_cast<float4*>(&xpout[m * NG + nB]) = oB;
        }
    }
}

// ---------------- fused 2-layer wavefront scan ----------------
// 256 CTAs, all co-resident (2/SM). bids 0..127: layer A (R12 scan, precomputed xp).
// bids 128..255: layer B (scan + in-step x-GEMM from layer A's output, gated per t).
// Per role: 32 cg x 4 bg; GEMM: 4 K-slices x 64 positions, 4 rows x 3 gates per thread.

__device__ __forceinline__ void gemm_acc(
    const float4* __restrict__ wz4, const float4* __restrict__ wr4,
    const float4* __restrict__ wh4,
    const float4* __restrict__ t0, const float4* __restrict__ t1,
    const float4* __restrict__ t2, const float4* __restrict__ t3,
    float aZ[4], float aR[4], float aH[4])
{
    #pragma unroll 4
    for (int k4 = 0; k4 < 16; k4++) {
        float4 wz = wz4[k4], wr = wr4[k4], wh = wh4[k4];
        float4 v0 = t0[k4], v1 = t1[k4], v2 = t2[k4], v3 = t3[k4];
        #define ROWF(rr, v)                                                        \
            aZ[rr]=fmaf(v.x,wz.x,aZ[rr]); aZ[rr]=fmaf(v.y,wz.y,aZ[rr]);            \
            aZ[rr]=fmaf(v.z,wz.z,aZ[rr]); aZ[rr]=fmaf(v.w,wz.w,aZ[rr]);            \
            aR[rr]=fmaf(v.x,wr.x,aR[rr]); aR[rr]=fmaf(v.y,wr.y,aR[rr]);            \
            aR[rr]=fmaf(v.z,wr.z,aR[rr]); aR[rr]=fmaf(v.w,wr.w,aR[rr]);            \
            aH[rr]=fmaf(v.x,wh.x,aH[rr]); aH[rr]=fmaf(v.y,wh.y,aH[rr]);            \
            aH[rr]=fmaf(v.z,wh.z,aH[rr]); aH[rr]=fmaf(v.w,wh.w,aH[rr]);
        ROWF(0, v0) ROWF(1, v1) ROWF(2, v2) ROWF(3, v3)
        #undef ROWF
    }
}

extern __shared__ float smem[];
__global__ __launch_bounds__(256, 2) void fused_scan(
    const float* __restrict__ WhA, const float* __restrict__ bhA, int layerA,
    const float* __restrict__ xp, float* __restrict__ outA,
    const float* __restrict__ WxB, const float* __restrict__ WhB,
    const float* __restrict__ bxB, const float* __restrict__ bhB,
    int layerB, float* __restrict__ outB)
{
    float* Wh_s = smem + SM_WH;
    float* Wx_s = smem + SM_WX;
    float* tile = smem + SM_TILE;
    float* red  = smem + SM_RED;

    int role = blockIdx.x >> 7;     // 0: layer A, 1: layer B
    int sid  = blockIdx.x & 127;
    int cg = sid & 31;
    int bg = sid >> 5;
    int tid = threadIdx.x;
    int u0 = cg * 8;
    int b0 = bg * 32;

    unsigned* barA  = g_bar + (layerA * T_LEN) * 4 + bg;
    unsigned* mybar = role ? (g_bar + (layerB * T_LEN) * 4 + bg) : barA;
    const float* Wh = role ? WhB : WhA;
    float* out      = role ? outB : outA;

    // GEMM-phase decode
    int ks  = tid >> 6;
    int pos = tid & 63;
    int ty2 = pos >> 3;
    int txg = pos & 7;
    // Epilogue decode
    int er = tid >> 3;
    int ej = tid & 7;
    int ep = (er >> 2) * 8 + ej;
    int erp = er & 3;

    // weight loads
    for (int idx = tid; idx < 24 * 256; idx += 256) {
        int col  = idx >> 8;
        int k    = idx & 255;
        int gate = col >> 3;
        int j    = col & 7;
        Wh_s[col * WHS + k] = Wh[(size_t)k * NG + gate * 256 + u0 + j];
    }
    if (role) {
        for (int idx = tid; idx < 24 * 256; idx += 256) {
            int col  = idx >> 8;
            int k    = idx & 255;
            int gate = col >> 3;
            int j    = col & 7;
            Wx_s[col * WHS + k] = WxB[(size_t)k * NG + gate * 256 + u0 + j];
        }
    }
    for (int i = tid; i < 32 * HSS + 32; i += 256) tile[i] = 0.f;

    int u = u0 + ej;
    int bglob = b0 + er;
    // biases
    float bz, br, bxh_ = 0.f, bhh_ = 0.f;
    if (role) {
        bz   = bxB[u] + bhB[u];
        br   = bxB[256 + u] + bhB[256 + u];
        bxh_ = bxB[512 + u];
        bhh_ = bhB[512 + u];
    } else {
        bz   = bhA[u];
        br   = bhA[256 + u];
        bhh_ = bhA[512 + u];
    }

    const float4* wz4 = reinterpret_cast<const float4*>(&Wh_s[(0 * 8 + txg) * WHS + ks * 64]);
    const float4* wr4 = reinterpret_cast<const float4*>(&Wh_s[(1 * 8 + txg) * WHS + ks * 64]);
    const float4* wh4 = reinterpret_cast<const float4*>(&Wh_s[(2 * 8 + txg) * WHS + ks * 64]);
    const float4* xz4 = reinterpret_cast<const float4*>(&Wx_s[(0 * 8 + txg) * WHS + ks * 64]);
    const float4* xr4 = reinterpret_cast<const float4*>(&Wx_s[(1 * 8 + txg) * WHS + ks * 64]);
    const float4* xh4 = reinterpret_cast<const float4*>(&Wx_s[(2 * 8 + txg) * WHS + ks * 64]);
    const float4* t0_4 = reinterpret_cast<const float4*>(tile + HROW(ty2 * 4 + 0)) + ks * 16;
    const float4* t1_4 = reinterpret_cast<const float4*>(tile + HROW(ty2 * 4 + 1)) + ks * 16;
    const float4* t2_4 = reinterpret_cast<const float4*>(tile + HROW(ty2 * 4 + 2)) + ks * 16;
    const float4* t3_4 = reinterpret_cast<const float4*>(tile + HROW(ty2 * 4 + 3)) + ks * 16;
    float* myred = &red[(ks * 64 + pos) * 16];

    float hprev = 0.f;

    // role A prologue: xp(t=0)
    float xz = 0.f, xr = 0.f, xh = 0.f;
    if (!role) {
        size_t xb0 = (size_t)bglob * NG;
        xz = __ldcs(&xp[xb0 + u]);
        xr = __ldcs(&xp[xb0 + 256 + u]);
        xh = __ldcs(&xp[xb0 + 512 + u]);
    }
    __syncthreads();

    for (int t = 0; t < T_LEN; t++) {
        float z, r, cand;
        if (!role) {
            // ---- role A: R12 step ----
            float nxz = 0.f, nxr = 0.f, nxh = 0.f;
            if (t + 1 < T_LEN) {
                size_t xb = ((size_t)(t + 1) * B_SZ + bglob) * NG;
                nxz = __ldcs(&xp[xb + u]);
                nxr = __ldcs(&xp[xb + 256 + u]);
                nxh = __ldcs(&xp[xb + 512 + u]);
            }
            float aZ[4] = {}, aR[4] = {}, aH[4] = {};
            gemm_acc(wz4, wr4, wh4, t0_4, t1_4, t2_4, t3_4, aZ, aR, aH);
            float4* r4 = reinterpret_cast<float4*>(myred);
            #pragma unroll
            for (int rr = 0; rr < 4; rr++)
                r4[rr] = make_float4(aZ[rr], aR[rr], aH[rr], 0.f);
            __syncthreads();

            float az = bz, ar = br, ah = bhh_;
            #pragma unroll
            for (int s = 0; s < 4; s++) {
                float4 rr = *reinterpret_cast<const float4*>(&red[(s * 64 + ep) * 16 + erp * 4]);
                az += rr.x; ar += rr.y; ah += rr.z;
            }
            z = __fdividef(1.f, 1.f + __expf(-(xz + az)));
            r = __fdividef(1.f, 1.f + __expf(-(xr + ar)));
            float e2 = __expf(2.f * (xh + r * ah));
            cand = 1.f - __fdividef(2.f, e2 + 1.f);
            xz = nxz; xr = nxr; xh = nxh;
        } else {
            // ---- role B: h-GEMM, gated x tile swap, x-GEMM ----
            float aZ[4] = {}, aR[4] = {}, aXH[4] = {}, aAH[4] = {};
            gemm_acc(wz4, wr4, wh4, t0_4, t1_4, t2_4, t3_4, aZ, aR, aAH);
            __syncthreads();              // done reading h tile
            if (tid == 0) {               // wait for layer A's x(t)
                unsigned v;
                const unsigned* a = &barA[t * 4];
                do {
                    asm volatile("ld.acquire.gpu.global.u32 %0, [%1];"
                                 : "=r"(v) : "l"(a) : "memory");
                } while (v < BG_CTAS);
            }
            __syncthreads();
            {   // load x_A(t) tile into shared tile buffer
                const float4* hg = reinterpret_cast<const float4*>(
                    &outA[((size_t)t * B_SZ + b0) * 256]);
                #pragma unroll
                for (int i = 0; i < 8; i++) {
                    int idx = tid + i * 256;
                    float4 v = __ldcg(&hg[idx]);
                    int row = idx >> 6, c4 = idx & 63;
                    reinterpret_cast<float4*>(tile + HROW(row))[c4] = v;
                }
            }
            __syncthreads();
            gemm_acc(xz4, xr4, xh4, t0_4, t1_4, t2_4, t3_4, aZ, aR, aXH);
            float4* r4 = reinterpret_cast<float4*>(myred);
            #pragma unroll
            for (int rr = 0; rr < 4; rr++)
                r4[rr] = make_float4(aZ[rr], aR[rr], aXH[rr], aAH[rr]);
            __syncthreads();

            float az = bz, ar = br, axh = bxh_, aah = bhh_;
            #pragma unroll
            for (int s = 0; s < 4; s++) {
                float4 rr = *reinterpret_cast<const float4*>(&red[(s * 64 + ep) * 16 + erp * 4]);
                az += rr.x; ar += rr.y; axh += rr.z; aah += rr.w;
            }
            z = __fdividef(1.f, 1.f + __expf(-az));
            r = __fdividef(1.f, 1.f + __expf(-ar));
            float e2 = __expf(2.f * (axh + r * aah));
            cand = 1.f - __fdividef(2.f, e2 + 1.f);
        }

        float hn = z * hprev + (1.f - z) * cand;
        hprev = hn;
        __stcg(&out[((size_t)t * B_SZ + bglob) * 256 + u], hn);

        __syncthreads();   // red reads done + all out stores ordered before release

        if (tid == 0) {    // role A arrives EVERY t (feeds role B's gate)
            unsigned* a = &mybar[t * 4];
            asm volatile("red.release.gpu.global.add.u32 [%0], %1;"
                         :: "l"(a), "r"(1u) : "memory");
            if (t < T_LEN - 1) {
                unsigned v;
                do {
                    asm volatile("ld.acquire.gpu.global.u32 %0, [%1];"
                                 : "=r"(v) : "l"(a) : "memory");
                } while (v < BG_CTAS);
            }
        }
        if (t < T_LEN - 1) {
            __syncthreads();
            // reload own-layer h(t) tile
            const float4* hg = reinterpret_cast<const float4*>(
                &out[((size_t)t * B_SZ + b0) * 256]);
            #pragma unroll
            for (int i = 0; i < 8; i++) {
                int idx = tid + i * 256;
                float4 v = __ldcg(&hg[idx]);
                int row = idx >> 6, c4 = idx & 63;
                reinterpret_cast<float4*>(tile + HROW(row))[c4] = v;
            }
            __syncthreads();
        }
    }
}

// ---------------- classifier head ----------------
__global__ void dense_kernel(const float* __restrict__ Wd1, const float* __restrict__ bd1,
                             const float* __restrict__ Wd2, const float* __restrict__ bd2,
                             const float* __restrict__ xin, float* __restrict__ out) {
    __shared__ float xs[256];
    __shared__ float red[256];
    int b = blockIdx.x;
    int j = threadIdx.x;
    xs[j] = xin[((size_t)(T_LEN - 1) * B_SZ + b) * 256 + j];
    __syncthreads();
    float acc = bd1[j];
    #pragma unroll 8
    for (int k = 0; k < 256; k++) acc = fmaf(xs[k], Wd1[k * 256 + j], acc);
    float h1 = acc > 0.f ? acc : 0.f;
    red[j] = h1 * Wd2[j];
    __syncthreads();
    for (int s = 128; s > 0; s >>= 1) {
        if (j < s) red[j] += red[j + s];
        __syncthreads();
    }
    if (j == 0) out[b] = 1.f / (1.f + expf(-(red[0] + bd2[0])));
}

// ---------------- launch ----------------
extern "C" void kernel_launch(void* const* d_in, const int* in_sizes, int n_in,
                              void* d_out, int out_size) {
    const int*   tokens = (const int*)  d_in[0];
    const float* emb    = (const float*)d_in[1];
    float* out = (float*)d_out;

    void*  bar_addr; cudaGetSymbolAddress(&bar_addr, g_bar);
    float* xA; cudaGetSymbolAddress((void**)&xA, g_xA);
    float* xB; cudaGetSymbolAddress((void**)&xB, g_xB);
    float* xp; cudaGetSymbolAddress((void**)&xp, g_xp);

    const int fused_smem = SM_TOT * (int)sizeof(float);   // 99712 B
    cudaFuncSetAttribute(fused_scan, cudaFuncAttributeMaxDynamicSharedMemorySize, fused_smem);

    cudaMemsetAsync(bar_addr, 0, sizeof(unsigned) * 4 * T_LEN * 4);

    embed_kernel<<<16384, 256>>>(tokens, emb, xA);

    // phase A: proj0 (emb->xp), then pipelined scans of layers 0 and 1
    {
        dim3 pgrid(512, 6);
        proj_kernel<<<pgrid, 256>>>((const float*)d_in[2], (const float*)d_in[4], xA, xp);
        fused_scan<<<256, 256, fused_smem>>>(
            (const float*)d_in[3], (const float*)d_in[5], 0, xp, xA,
            (const float*)d_in[6], (const float*)d_in[7],
            (const float*)d_in[8], (const float*)d_in[9], 1, xB);
    }
    // phase B: proj2 (x1->xp), then pipelined scans of layers 2 and 3
    {
        dim3 pgrid(512, 6);
        proj_kernel<<<pgrid, 256>>>((const float*)d_in[10], (const float*)d_in[12], xB, xp);
        fused_scan<<<256, 256, fused_smem>>>(
            (const float*)d_in[11], (const float*)d_in[13], 2, xp, xA,
            (const float*)d_in[14], (const float*)d_in[15],
            (const float*)d_in[16], (const float*)d_in[17], 3, xB);
    }

    dense_kernel<<<128, 256>>>((const float*)d_in[18], (const float*)d_in[19],
                               (const float*)d_in[20], (const float*)d_in[21], xB, out);
}